// round 10
// baseline (speedup 1.0000x reference)
#include <cuda_runtime.h>
#include <cuda_bf16.h>
#include <cstdint>

#define N_NODES 100000
#define N_EDGES 625000
#define D_IN    128
#define D_HID   256

// ---------------------------------------------------------------------------
// Scratch (__device__ globals; allocation-free rule)
// ---------------------------------------------------------------------------
__device__ float g_agg[(size_t)N_NODES * D_IN];
__device__ float g_cnt[N_NODES];
// Weight image W_cat^T: [img: hi/lo][n (256)][k (256)] bf16 (512B rows).
__device__ __nv_bfloat16 g_Wt[2][256 * 256];

// ---------------------------------------------------------------------------
// Kernel 0: zero scratch
// ---------------------------------------------------------------------------
__global__ void zero_kernel() {
    int i = blockIdx.x * blockDim.x + threadIdx.x;
    int stride = gridDim.x * blockDim.x;
    const int total4 = N_NODES * D_IN / 4;
    float4 z = make_float4(0.f, 0.f, 0.f, 0.f);
    for (int j = i; j < total4; j += stride)
        ((float4*)g_agg)[j] = z;
    for (int j = i; j < N_NODES; j += stride)
        g_cnt[j] = 0.f;
}

// ---------------------------------------------------------------------------
// Kernel 1: edge scatter. One warp per edge, RED.128 vector reductions.
// ---------------------------------------------------------------------------
__global__ void edge_kernel(const float* __restrict__ x,
                            const int* __restrict__ ei) {
    int w = blockIdx.x * (blockDim.x >> 5) + (threadIdx.x >> 5);
    if (w >= N_EDGES) return;
    int lane = threadIdx.x & 31;

    int src = ei[w];
    int dst = ei[N_EDGES + w];

    float4 v = ((const float4*)(x + (long long)src * D_IN))[lane];
    float* p = g_agg + (long long)dst * D_IN + lane * 4;
    asm volatile("red.global.add.v4.f32 [%0], {%1,%2,%3,%4};"
                 :: "l"(p), "f"(v.x), "f"(v.y), "f"(v.z), "f"(v.w)
                 : "memory");
    if (lane == 0)
        atomicAdd(&g_cnt[dst], 1.0f);
}

// ---------------------------------------------------------------------------
// Kernel 2: build bf16 hi/lo weight image (W_cat^T, [n][k] layout)
// ---------------------------------------------------------------------------
__global__ void wconv_kernel(const float* __restrict__ wl,
                             const float* __restrict__ wr) {
    int idx = blockIdx.x * blockDim.x + threadIdx.x;
    if (idx >= 256 * 256) return;
    int n = idx >> 8;
    int k = idx & 255;
    float v = (k < 128) ? wl[k * 256 + n] : wr[(k - 128) * 256 + n];
    __nv_bfloat16 hi = __float2bfloat16_rn(v);
    __nv_bfloat16 lo = __float2bfloat16_rn(v - __bfloat162float(hi));
    g_Wt[0][idx] = hi;
    g_Wt[1][idx] = lo;
}

// ---------------------------------------------------------------------------
// PTX helpers (family-portable: sm_75/80+)
// ---------------------------------------------------------------------------
__device__ __forceinline__ uint32_t smem_u32(const void* p) {
    uint32_t a;
    asm("{ .reg .u64 t; cvta.to.shared.u64 t, %1; cvt.u32.u64 %0, t; }"
        : "=r"(a) : "l"(p));
    return a;
}
__device__ __forceinline__ void mma_bf16(float* d, const uint32_t* a,
                                         uint32_t b0, uint32_t b1) {
    asm volatile(
        "mma.sync.aligned.m16n8k16.row.col.f32.bf16.bf16.f32 "
        "{%0,%1,%2,%3}, {%4,%5,%6,%7}, {%8,%9}, {%0,%1,%2,%3};"
        : "+f"(d[0]), "+f"(d[1]), "+f"(d[2]), "+f"(d[3])
        : "r"(a[0]), "r"(a[1]), "r"(a[2]), "r"(a[3]), "r"(b0), "r"(b1));
}
#define LDSM4(d0, d1, d2, d3, addr) \
    asm volatile("ldmatrix.sync.aligned.m8n8.x4.shared.b16 {%0,%1,%2,%3}, [%4];" \
        : "=r"(d0), "=r"(d1), "=r"(d2), "=r"(d3) : "r"(addr))
#define CPASYNC16(dst, src) \
    asm volatile("cp.async.ca.shared.global [%0], [%1], 16;" :: "r"(dst), "l"(src))
#define CPCOMMIT() asm volatile("cp.async.commit_group;" ::: "memory")
#define CPWAIT0()  asm volatile("cp.async.wait_group 0;" ::: "memory")

// ---------------------------------------------------------------------------
// Kernel 3: bf16 hi/lo 3-pass mma.sync node kernel, 3 CTAs/SM (24 warps).
// Block = 256 threads (8 warps), M=32 nodes, N=256, K=256 in 8 chunks of 32.
// Warp tile M32 x N32 (acc = 32 regs -> <=85 regs -> 3 CTAs/SM).
// A double-buffered; B single-buffered cp.async; register epilogue.
//
// SMEM/CTA (52,480 B -> 3 CTAs/SM by regs, 4 by smem):
//   A bufs [2 buf][2 img][32 rows][40 halfs] @ 0        (10,240)
//   B buf  [2 img][256 rows][40 halfs]       @ 10,240   (40,960)
//   s_bl [256] f32                           @ 51,200
//   s_inv [32] f32                           @ 52,224
//   epilogue overlays A/B: s_part [8][32][16] @0 (16K); s_wh @16,384;
//                          s_bh @33,792
// ---------------------------------------------------------------------------
#define AST     80            // bytes per smem row (32 halfs + 16B pad)
#define A_IMG   2560          // 32*80
#define A_BUF   5120          // 2 imgs
#define B_OFF   10240
#define B_IMG   20480         // 256*80
#define OFF_BL  51200
#define OFF_INV 52224
#define SMEM_DYN 52480
#define E_WH  16384
#define E_BH  33792

__global__ __launch_bounds__(256, 3) void node_mma_kernel(
    const float* __restrict__ x,
    const float* __restrict__ wp, const float* __restrict__ bp,
    const float* __restrict__ ws, const float* __restrict__ bs,
    const float* __restrict__ bl,
    float* __restrict__ out)
{
    extern __shared__ float4 smem4[];
    char* smem = (char*)smem4;
    const uint32_t sb = smem_u32(smem);
    float* s_bl  = (float*)(smem + OFF_BL);
    float* s_inv = (float*)(smem + OFF_INV);

    const int t    = threadIdx.x;
    const int w    = t >> 5;
    const int lane = t & 31;
    const int lq   = lane >> 2;
    const int lr   = (lane & 3) * 2;
    const long long base = (long long)blockIdx.x * 32;

    if (t < 32) {
        long long node = base + t;
        if (node >= N_NODES) node = N_NODES - 1;
        s_inv[t] = 1.0f / fmaxf(g_cnt[node], 1.0f);
    }
    if (t < 256) s_bl[t] = bl[t];
    __syncthreads();

    const int nbase = w * 32;          // warp's N-strip (N32)

    float acc[32];                     // [mi(2)][nt(4)][4]
#pragma unroll
    for (int i = 0; i < 32; i++) acc[i] = 0.f;

    // ---- staging helpers (k=32 chunks) ----
    auto stageB = [&](int c) {         // 2 img x 256 rows x 64B via cp.async
#pragma unroll
        for (int img = 0; img < 2; img++) {
            const char* gs = (const char*)&g_Wt[img][0];
#pragma unroll
            for (int it = 0; it < 4; it++) {
                int i = t + it * 256;  // 0..1023
                int n = i >> 2, q = i & 3;
                uint32_t dst = sb + B_OFF + img * B_IMG + n * AST + q * 16;
                CPASYNC16(dst, gs + n * 512 + c * 64 + q * 16);
            }
        }
    };
    auto stageA = [&](int c, int buf) {   // 32 rows x 32 k = 256 float4
        if (t < 256) {
            int m = t >> 3, kl = (t & 7) * 4;
            long long node = base + m;
            if (node >= N_NODES) node = N_NODES - 1;
            const float* src = (c < 4)
                ? (g_agg + node * D_IN + c * 32 + kl)
                : (x + node * D_IN + (c - 4) * 32 + kl);
            float4 vv = *(const float4*)src;
            if (c < 4) {
                float inv = s_inv[m];
                vv.x *= inv; vv.y *= inv; vv.z *= inv; vv.w *= inv;
            }
            __nv_bfloat16 h0 = __float2bfloat16_rn(vv.x);
            __nv_bfloat16 h1 = __float2bfloat16_rn(vv.y);
            __nv_bfloat16 h2 = __float2bfloat16_rn(vv.z);
            __nv_bfloat16 h3 = __float2bfloat16_rn(vv.w);
            __nv_bfloat16 l0 = __float2bfloat16_rn(vv.x - __bfloat162float(h0));
            __nv_bfloat16 l1 = __float2bfloat16_rn(vv.y - __bfloat162float(h1));
            __nv_bfloat16 l2 = __float2bfloat16_rn(vv.z - __bfloat162float(h2));
            __nv_bfloat16 l3 = __float2bfloat16_rn(vv.w - __bfloat162float(h3));
            uint2 hp, lp;
            hp.x = (uint32_t)__bfloat16_as_ushort(h0) | ((uint32_t)__bfloat16_as_ushort(h1) << 16);
            hp.y = (uint32_t)__bfloat16_as_ushort(h2) | ((uint32_t)__bfloat16_as_ushort(h3) << 16);
            lp.x = (uint32_t)__bfloat16_as_ushort(l0) | ((uint32_t)__bfloat16_as_ushort(l1) << 16);
            lp.y = (uint32_t)__bfloat16_as_ushort(l2) | ((uint32_t)__bfloat16_as_ushort(l3) << 16);
            char* p = smem + buf * A_BUF + m * AST + kl * 2;
            *(uint2*)p = hp;
            *(uint2*)(p + A_IMG) = lp;
        }
    };

    // ---- prologue ----
    stageA(0, 0);

    const int tt    = lane >> 3;
    const int arow  = ((tt & 1) * 8) + (lane & 7);
    const int acol2 = ((tt >> 1) * 8) * 2;

    // ---- mainloop: 8 chunks; B single-buffered (cross-CTA hiding) ----
    for (int c = 0; c < 8; c++) {
        int cur = c & 1, nxt = cur ^ 1;
        __syncthreads();                  // prior MMAs done with B + A(alt)
        stageB(c); CPCOMMIT();
        if (c < 7) stageA(c + 1, nxt);    // overlaps B DMA
        CPWAIT0();
        __syncthreads();                  // B(c) + A(c) visible

        const uint32_t Abase = sb + cur * A_BUF;
        const uint32_t Bbase = sb + B_OFF;
#pragma unroll
        for (int pass = 0; pass < 3; pass++) {
            uint32_t Ab = Abase + ((pass == 2) ? A_IMG : 0);
            uint32_t Bb = Bbase + ((pass == 1) ? B_IMG : 0);
#pragma unroll
            for (int ks = 0; ks < 2; ks++) {
                int kb = ks * 32;         // 16 halfs = 32B per k-step
                uint32_t a0[4], a1[4], b[2][4];
                uint32_t ad = Ab + arow * AST + kb + acol2;
                LDSM4(a0[0], a0[1], a0[2], a0[3], ad);
                LDSM4(a1[0], a1[1], a1[2], a1[3], ad + 16 * AST);
#pragma unroll
                for (int j = 0; j < 2; j++) {
                    uint32_t bd = Bb + (nbase + j * 16 + arow) * AST + kb + acol2;
                    LDSM4(b[j][0], b[j][1], b[j][2], b[j][3], bd);
                }
#pragma unroll
                for (int j = 0; j < 2; j++) {
                    int nt0 = j * 2, nt1 = j * 2 + 1;
                    mma_bf16(acc + nt0 * 4,      a0, b[j][0], b[j][2]);
                    mma_bf16(acc + nt1 * 4,      a0, b[j][1], b[j][3]);
                    mma_bf16(acc + 16 + nt0 * 4, a1, b[j][0], b[j][2]);
                    mma_bf16(acc + 16 + nt1 * 4, a1, b[j][1], b[j][3]);
                }
            }
        }
    }
    __syncthreads();

    // ---- epilogue: overlay A/B region (register-resident heads) ----
    float* s_part = (float*)smem;              // [8 nstrip][32 m][16]
    float* s_wh   = (float*)(smem + E_WH);     // [256][17]
    float* s_bh   = (float*)(smem + E_BH);

    for (int i = t; i < 13 * 256; i += 256) {
        int j = i & 255, cc = i >> 8;
        s_wh[j * 17 + cc] = (cc < 7) ? wp[j * 7 + cc] : ws[j * 6 + (cc - 7)];
    }
    if (t < 16) s_bh[t] = (t < 7) ? bp[t] : (t < 13 ? bs[t - 7] : 0.f);
    __syncthreads();

#pragma unroll
    for (int mi = 0; mi < 2; mi++) {
        float pr0[13], pr1[13];
#pragma unroll
        for (int cc = 0; cc < 13; cc++) { pr0[cc] = 0.f; pr1[cc] = 0.f; }
#pragma unroll
        for (int nt = 0; nt < 4; nt++) {
            int col0 = nbase + nt * 8 + lr;
            float b0 = s_bl[col0], b1 = s_bl[col0 + 1];
            const float* d = acc + mi * 16 + nt * 4;
            float h00 = fmaxf(d[0] + b0, 0.f), h01 = fmaxf(d[1] + b1, 0.f);
            float h10 = fmaxf(d[2] + b0, 0.f), h11 = fmaxf(d[3] + b1, 0.f);
            const float* w0 = s_wh + col0 * 17;
            const float* w1 = w0 + 17;
#pragma unroll
            for (int cc = 0; cc < 13; cc++) {
                float wa = w0[cc], wb = w1[cc];
                pr0[cc] = fmaf(h00, wa, fmaf(h01, wb, pr0[cc]));
                pr1[cc] = fmaf(h10, wa, fmaf(h11, wb, pr1[cc]));
            }
        }
#pragma unroll
        for (int cc = 0; cc < 13; cc++) {
            pr0[cc] += __shfl_xor_sync(0xffffffff, pr0[cc], 1);
            pr0[cc] += __shfl_xor_sync(0xffffffff, pr0[cc], 2);
            pr1[cc] += __shfl_xor_sync(0xffffffff, pr1[cc], 1);
            pr1[cc] += __shfl_xor_sync(0xffffffff, pr1[cc], 2);
        }
        if ((lane & 3) == 0) {
            int r = mi * 16 + lq;
#pragma unroll
            for (int cc = 0; cc < 13; cc++) {
                s_part[w * 512 + r * 16 + cc]       = pr0[cc];
                s_part[w * 512 + (r + 8) * 16 + cc] = pr1[cc];
            }
        }
    }
    __syncthreads();

    // final reduce over 8 N-strips + log_softmax + writeout
    if (t < 32) {
        long long node = base + t;
        if (node < N_NODES) {
            float o[13];
#pragma unroll
            for (int cc = 0; cc < 13; cc++) {
                float s = s_bh[cc];
#pragma unroll
                for (int st = 0; st < 8; st++)
                    s += s_part[st * 512 + t * 16 + cc];
                o[cc] = s;
            }
            float mx = o[0];
#pragma unroll
            for (int cc = 1; cc < 7; cc++) mx = fmaxf(mx, o[cc]);
            float s = 0.f;
#pragma unroll
            for (int cc = 0; cc < 7; cc++) s += __expf(o[cc] - mx);
            float lse = mx + __logf(s);
#pragma unroll
            for (int cc = 0; cc < 7; cc++) out[node * 7 + cc] = o[cc] - lse;

            mx = o[7];
#pragma unroll
            for (int cc = 8; cc < 13; cc++) mx = fmaxf(mx, o[cc]);
            s = 0.f;
#pragma unroll
            for (int cc = 7; cc < 13; cc++) s += __expf(o[cc] - mx);
            lse = mx + __logf(s);
            float* out2 = out + (long long)N_NODES * 7;
#pragma unroll
            for (int cc = 0; cc < 6; cc++) out2[node * 6 + cc] = o[7 + cc] - lse;
        }
    }
}

// ---------------------------------------------------------------------------
extern "C" void kernel_launch(void* const* d_in, const int* in_sizes, int n_in,
                              void* d_out, int out_size) {
    const float* x  = (const float*)d_in[0];
    const int*   ei = (const int*)d_in[1];
    const float* wl = (const float*)d_in[2];
    const float* bl = (const float*)d_in[3];
    const float* wr = (const float*)d_in[4];
    const float* wp = (const float*)d_in[5];
    const float* bp = (const float*)d_in[6];
    const float* ws = (const float*)d_in[7];
    const float* bs = (const float*)d_in[8];
    float* out = (float*)d_out;

    cudaFuncSetAttribute(node_mma_kernel,
                         cudaFuncAttributeMaxDynamicSharedMemorySize, SMEM_DYN);

    zero_kernel<<<512, 256>>>();
    wconv_kernel<<<256, 256>>>(wl, wr);

    int edge_blocks = (N_EDGES + 7) / 8;   // one warp per edge
    edge_kernel<<<edge_blocks, 256>>>(x, ei);

    int node_blocks = (N_NODES + 31) / 32;   // 3125
    node_mma_kernel<<<node_blocks, 256, SMEM_DYN>>>(x, wp, bp, ws, bs, bl, out);
}

// round 11
// speedup vs baseline: 1.3690x; 1.3690x over previous
#include <cuda_runtime.h>
#include <cuda_fp16.h>
#include <cstdint>

#define N_NODES 100000
#define N_EDGES 625000
#define D_IN    128
#define D_HID   256

// ---------------------------------------------------------------------------
// Scratch (__device__ globals; allocation-free rule)
// ---------------------------------------------------------------------------
__device__ float g_agg[(size_t)N_NODES * D_IN];
__device__ float g_cnt[N_NODES];
// Weight image W_cat^T: [n (256)][k (256)] fp16 (512B rows).
// k<128 -> w_l[k][n], k>=128 -> w_r[k-128][n].
__device__ __half g_Wh[256 * 256];

// ---------------------------------------------------------------------------
// Kernel 0: zero scratch
// ---------------------------------------------------------------------------
__global__ void zero_kernel() {
    int i = blockIdx.x * blockDim.x + threadIdx.x;
    int stride = gridDim.x * blockDim.x;
    const int total4 = N_NODES * D_IN / 4;
    float4 z = make_float4(0.f, 0.f, 0.f, 0.f);
    for (int j = i; j < total4; j += stride)
        ((float4*)g_agg)[j] = z;
    for (int j = i; j < N_NODES; j += stride)
        g_cnt[j] = 0.f;
}

// ---------------------------------------------------------------------------
// Kernel 1: edge scatter. One warp per edge, RED.128 vector reductions.
// ---------------------------------------------------------------------------
__global__ void edge_kernel(const float* __restrict__ x,
                            const int* __restrict__ ei) {
    int w = blockIdx.x * (blockDim.x >> 5) + (threadIdx.x >> 5);
    if (w >= N_EDGES) return;
    int lane = threadIdx.x & 31;

    int src = ei[w];
    int dst = ei[N_EDGES + w];

    float4 v = ((const float4*)(x + (long long)src * D_IN))[lane];
    float* p = g_agg + (long long)dst * D_IN + lane * 4;
    asm volatile("red.global.add.v4.f32 [%0], {%1,%2,%3,%4};"
                 :: "l"(p), "f"(v.x), "f"(v.y), "f"(v.z), "f"(v.w)
                 : "memory");
    if (lane == 0)
        atomicAdd(&g_cnt[dst], 1.0f);
}

// ---------------------------------------------------------------------------
// Kernel 2: build fp16 weight image (W_cat^T, [n][k] layout, single image)
// ---------------------------------------------------------------------------
__global__ void wconv_kernel(const float* __restrict__ wl,
                             const float* __restrict__ wr) {
    int idx = blockIdx.x * blockDim.x + threadIdx.x;
    if (idx >= 256 * 256) return;
    int n = idx >> 8;
    int k = idx & 255;
    float v = (k < 128) ? wl[k * 256 + n] : wr[(k - 128) * 256 + n];
    g_Wh[idx] = __float2half_rn(v);
}

// ---------------------------------------------------------------------------
// PTX helpers (family-portable: sm_75/80+)
// ---------------------------------------------------------------------------
__device__ __forceinline__ uint32_t smem_u32(const void* p) {
    uint32_t a;
    asm("{ .reg .u64 t; cvta.to.shared.u64 t, %1; cvt.u32.u64 %0, t; }"
        : "=r"(a) : "l"(p));
    return a;
}
__device__ __forceinline__ void mma_f16(float* d, const uint32_t* a,
                                        uint32_t b0, uint32_t b1) {
    asm volatile(
        "mma.sync.aligned.m16n8k16.row.col.f32.f16.f16.f32 "
        "{%0,%1,%2,%3}, {%4,%5,%6,%7}, {%8,%9}, {%0,%1,%2,%3};"
        : "+f"(d[0]), "+f"(d[1]), "+f"(d[2]), "+f"(d[3])
        : "r"(a[0]), "r"(a[1]), "r"(a[2]), "r"(a[3]), "r"(b0), "r"(b1));
}
#define LDSM4(d0, d1, d2, d3, addr) \
    asm volatile("ldmatrix.sync.aligned.m8n8.x4.shared.b16 {%0,%1,%2,%3}, [%4];" \
        : "=r"(d0), "=r"(d1), "=r"(d2), "=r"(d3) : "r"(addr))
#define CPASYNC16(dst, src) \
    asm volatile("cp.async.ca.shared.global [%0], [%1], 16;" :: "r"(dst), "l"(src))
#define CPCOMMIT() asm volatile("cp.async.commit_group;" ::: "memory")
#define CPWAIT0()  asm volatile("cp.async.wait_group 0;" ::: "memory")

// ---------------------------------------------------------------------------
// Kernel 3: fp16 2-pass mma.sync node kernel (A split hi/lo, B single image).
// Block = 256 threads (8 warps), M=64 nodes, N=256, K=256 in 8 chunks of 32.
// Warp tile M32 x N64. A and B double-buffered; register epilogue.
//
// SMEM/CTA (62,720 B; regs cap at 2 CTAs/SM -> 16 warps):
//   A bufs [2 buf][2 img(hi/lo)][64 rows][40 halfs] @ 0   (20,480)
//   B bufs [2 buf][256 rows][40 halfs]   @ 20,480         (40,960)
//   s_bl [256] f32                       @ 61,440
//   s_inv [64] f32                       @ 62,464
//   epilogue overlays: s_part 16K @0; s_wh @16,384; s_bh @33,792
// ---------------------------------------------------------------------------
#define AST     80            // bytes per smem row (32 halfs + 16B pad)
#define A_IMG   5120          // 64*80
#define A_BUF   10240         // 2 imgs
#define B_OFF   20480
#define B_IMG   20480         // 256*80 (single image per buffer)
#define OFF_BL  61440
#define OFF_INV 62464
#define SMEM_DYN 62720
#define E_WH  16384
#define E_BH  33792

__global__ __launch_bounds__(256, 2) void node_mma_kernel(
    const float* __restrict__ x,
    const float* __restrict__ wp, const float* __restrict__ bp,
    const float* __restrict__ ws, const float* __restrict__ bs,
    const float* __restrict__ bl,
    float* __restrict__ out)
{
    extern __shared__ float4 smem4[];
    char* smem = (char*)smem4;
    const uint32_t sb = smem_u32(smem);
    float* s_bl  = (float*)(smem + OFF_BL);
    float* s_inv = (float*)(smem + OFF_INV);

    const int t    = threadIdx.x;
    const int w    = t >> 5;
    const int lane = t & 31;
    const int lq   = lane >> 2;
    const int lr   = (lane & 3) * 2;
    const long long base = (long long)blockIdx.x * 64;

    if (t < 64) {
        long long node = base + t;
        if (node >= N_NODES) node = N_NODES - 1;
        s_inv[t] = 1.0f / fmaxf(g_cnt[node], 1.0f);
    }
    if (t < 256) s_bl[t] = bl[t];
    __syncthreads();

    const int m0    = (w & 1) * 32;    // 2 M-strips
    const int nbase = (w >> 1) * 64;   // 4 N-strips

    float acc[64];
#pragma unroll
    for (int i = 0; i < 64; i++) acc[i] = 0.f;

    // ---- staging helpers (k=32 chunks) ----
    auto stageB = [&](int c, int buf) {   // 256 rows x 64B via cp.async
        const char* gs = (const char*)&g_Wh[0];
#pragma unroll
        for (int it = 0; it < 4; it++) {
            int i = t + it * 256;         // 0..1023
            int n = i >> 2, q = i & 3;
            uint32_t dst = sb + B_OFF + buf * B_IMG + n * AST + q * 16;
            CPASYNC16(dst, gs + n * 512 + c * 64 + q * 16);
        }
    };
    auto stageA = [&](int c, int buf) {   // 64 rows x 32 k = 512 float4
#pragma unroll
        for (int it = 0; it < 2; it++) {
            int i = t + it * 256;         // 0..511
            int m = i >> 3, kl = (i & 7) * 4;
            long long node = base + m;
            if (node >= N_NODES) node = N_NODES - 1;
            const float* src = (c < 4)
                ? (g_agg + node * D_IN + c * 32 + kl)
                : (x + node * D_IN + (c - 4) * 32 + kl);
            float4 vv = *(const float4*)src;
            if (c < 4) {
                float inv = s_inv[m];
                vv.x *= inv; vv.y *= inv; vv.z *= inv; vv.w *= inv;
            }
            __half h0 = __float2half_rn(vv.x);
            __half h1 = __float2half_rn(vv.y);
            __half h2 = __float2half_rn(vv.z);
            __half h3 = __float2half_rn(vv.w);
            __half l0 = __float2half_rn(vv.x - __half2float(h0));
            __half l1 = __float2half_rn(vv.y - __half2float(h1));
            __half l2 = __float2half_rn(vv.z - __half2float(h2));
            __half l3 = __float2half_rn(vv.w - __half2float(h3));
            uint2 hp, lp;
            hp.x = (uint32_t)__half_as_ushort(h0) | ((uint32_t)__half_as_ushort(h1) << 16);
            hp.y = (uint32_t)__half_as_ushort(h2) | ((uint32_t)__half_as_ushort(h3) << 16);
            lp.x = (uint32_t)__half_as_ushort(l0) | ((uint32_t)__half_as_ushort(l1) << 16);
            lp.y = (uint32_t)__half_as_ushort(l2) | ((uint32_t)__half_as_ushort(l3) << 16);
            char* p = smem + buf * A_BUF + m * AST + kl * 2;
            *(uint2*)p = hp;
            *(uint2*)(p + A_IMG) = lp;
        }
    };

    // ---- prologue: chunk 0 into buffer 0 ----
    stageB(0, 0); CPCOMMIT();
    stageA(0, 0);
    CPWAIT0();
    __syncthreads();

    const int tt    = lane >> 3;
    const int arow  = ((tt & 1) * 8) + (lane & 7);
    const int acol2 = ((tt >> 1) * 8) * 2;

    // ---- mainloop: 8 chunks, DMA for c+1 overlaps MMAs of c ----
    for (int c = 0; c < 8; c++) {
        int cur = c & 1, nxt = cur ^ 1;
        if (c < 7) {
            stageB(c + 1, nxt); CPCOMMIT();
            stageA(c + 1, nxt);
        }

        const uint32_t Abase = sb + cur * A_BUF;
        const uint32_t Bb    = sb + B_OFF + cur * B_IMG;
#pragma unroll
        for (int pass = 0; pass < 2; pass++) {      // pass0: A_hi, pass1: A_lo
            uint32_t Ab = Abase + pass * A_IMG;
#pragma unroll
            for (int ks = 0; ks < 2; ks++) {
                int kb = ks * 32;         // 16 halfs = 32B per k-step
                uint32_t a0[4], a1[4], b[4][4];
                uint32_t ad = Ab + (m0 + arow) * AST + kb + acol2;
                LDSM4(a0[0], a0[1], a0[2], a0[3], ad);
                LDSM4(a1[0], a1[1], a1[2], a1[3], ad + 16 * AST);
#pragma unroll
                for (int j = 0; j < 4; j++) {
                    uint32_t bd = Bb + (nbase + j * 16 + arow) * AST + kb + acol2;
                    LDSM4(b[j][0], b[j][1], b[j][2], b[j][3], bd);
                }
#pragma unroll
                for (int j = 0; j < 4; j++) {
                    int nt0 = j * 2, nt1 = j * 2 + 1;
                    mma_f16(acc + nt0 * 4,      a0, b[j][0], b[j][2]);
                    mma_f16(acc + nt1 * 4,      a0, b[j][1], b[j][3]);
                    mma_f16(acc + 32 + nt0 * 4, a1, b[j][0], b[j][2]);
                    mma_f16(acc + 32 + nt1 * 4, a1, b[j][1], b[j][3]);
                }
            }
        }
        if (c < 7) CPWAIT0();
        __syncthreads();
    }

    // ---- epilogue: overlay A/B region (register-resident heads) ----
    float* s_part = (float*)smem;              // [4 nstrip][64 m][16]
    float* s_wh   = (float*)(smem + E_WH);     // [256][17]
    float* s_bh   = (float*)(smem + E_BH);

    for (int i = t; i < 13 * 256; i += 256) {
        int j = i & 255, cc = i >> 8;
        s_wh[j * 17 + cc] = (cc < 7) ? wp[j * 7 + cc] : ws[j * 6 + (cc - 7)];
    }
    if (t < 16) s_bh[t] = (t < 7) ? bp[t] : (t < 13 ? bs[t - 7] : 0.f);
    __syncthreads();

    const int nstrip = w >> 1;
#pragma unroll
    for (int mi = 0; mi < 2; mi++) {
        float pr0[13], pr1[13];
#pragma unroll
        for (int cc = 0; cc < 13; cc++) { pr0[cc] = 0.f; pr1[cc] = 0.f; }
#pragma unroll
        for (int nt = 0; nt < 8; nt++) {
            int col0 = nbase + nt * 8 + lr;
            float b0 = s_bl[col0], b1 = s_bl[col0 + 1];
            const float* d = acc + mi * 32 + nt * 4;
            float h00 = fmaxf(d[0] + b0, 0.f), h01 = fmaxf(d[1] + b1, 0.f);
            float h10 = fmaxf(d[2] + b0, 0.f), h11 = fmaxf(d[3] + b1, 0.f);
            const float* w0 = s_wh + col0 * 17;
            const float* w1 = w0 + 17;
#pragma unroll
            for (int cc = 0; cc < 13; cc++) {
                float wa = w0[cc], wb = w1[cc];
                pr0[cc] = fmaf(h00, wa, fmaf(h01, wb, pr0[cc]));
                pr1[cc] = fmaf(h10, wa, fmaf(h11, wb, pr1[cc]));
            }
        }
#pragma unroll
        for (int cc = 0; cc < 13; cc++) {
            pr0[cc] += __shfl_xor_sync(0xffffffff, pr0[cc], 1);
            pr0[cc] += __shfl_xor_sync(0xffffffff, pr0[cc], 2);
            pr1[cc] += __shfl_xor_sync(0xffffffff, pr1[cc], 1);
            pr1[cc] += __shfl_xor_sync(0xffffffff, pr1[cc], 2);
        }
        if ((lane & 3) == 0) {
            int r = m0 + mi * 16 + lq;
#pragma unroll
            for (int cc = 0; cc < 13; cc++) {
                s_part[nstrip * 1024 + r * 16 + cc]       = pr0[cc];
                s_part[nstrip * 1024 + (r + 8) * 16 + cc] = pr1[cc];
            }
        }
    }
    __syncthreads();

    // final reduce + log_softmax + writeout
    if (t < 64) {
        long long node = base + t;
        if (node < N_NODES) {
            float o[13];
#pragma unroll
            for (int cc = 0; cc < 13; cc++) {
                o[cc] = s_bh[cc] + s_part[t * 16 + cc] + s_part[1024 + t * 16 + cc]
                      + s_part[2048 + t * 16 + cc] + s_part[3072 + t * 16 + cc];
            }
            float mx = o[0];
#pragma unroll
            for (int cc = 1; cc < 7; cc++) mx = fmaxf(mx, o[cc]);
            float s = 0.f;
#pragma unroll
            for (int cc = 0; cc < 7; cc++) s += __expf(o[cc] - mx);
            float lse = mx + __logf(s);
#pragma unroll
            for (int cc = 0; cc < 7; cc++) out[node * 7 + cc] = o[cc] - lse;

            mx = o[7];
#pragma unroll
            for (int cc = 8; cc < 13; cc++) mx = fmaxf(mx, o[cc]);
            s = 0.f;
#pragma unroll
            for (int cc = 7; cc < 13; cc++) s += __expf(o[cc] - mx);
            lse = mx + __logf(s);
            float* out2 = out + (long long)N_NODES * 7;
#pragma unroll
            for (int cc = 0; cc < 6; cc++) out2[node * 6 + cc] = o[7 + cc] - lse;
        }
    }
}

// ---------------------------------------------------------------------------
extern "C" void kernel_launch(void* const* d_in, const int* in_sizes, int n_in,
                              void* d_out, int out_size) {
    const float* x  = (const float*)d_in[0];
    const int*   ei = (const int*)d_in[1];
    const float* wl = (const float*)d_in[2];
    const float* bl = (const float*)d_in[3];
    const float* wr = (const float*)d_in[4];
    const float* wp = (const float*)d_in[5];
    const float* bp = (const float*)d_in[6];
    const float* ws = (const float*)d_in[7];
    const float* bs = (const float*)d_in[8];
    float* out = (float*)d_out;

    cudaFuncSetAttribute(node_mma_kernel,
                         cudaFuncAttributeMaxDynamicSharedMemorySize, SMEM_DYN);

    zero_kernel<<<512, 256>>>();
    wconv_kernel<<<256, 256>>>(wl, wr);

    int edge_blocks = (N_EDGES + 7) / 8;   // one warp per edge
    edge_kernel<<<edge_blocks, 256>>>(x, ei);

    int node_blocks = (N_NODES + 63) / 64;   // 1563
    node_mma_kernel<<<node_blocks, 256, SMEM_DYN>>>(x, wp, bp, ws, bs, bl, out);
}

// round 12
// speedup vs baseline: 1.6007x; 1.1692x over previous
#include <cuda_runtime.h>
#include <cuda_fp16.h>
#include <cstdint>

#define N_NODES 100000
#define N_EDGES 625000
#define D_IN    128
#define D_HID   256

// ---------------------------------------------------------------------------
// Scratch (__device__ globals; allocation-free rule)
// ---------------------------------------------------------------------------
__device__ float g_agg[(size_t)N_NODES * D_IN];
__device__ float g_cnt[N_NODES];
// Weight image W_cat^T: [n (256)][k (256)] fp16 (512B rows).
// k<128 -> w_l[k][n], k>=128 -> w_r[k-128][n].
__device__ __half g_Wh[256 * 256];

// ---------------------------------------------------------------------------
// Kernel 0: zero scratch
// ---------------------------------------------------------------------------
__global__ void zero_kernel() {
    int i = blockIdx.x * blockDim.x + threadIdx.x;
    int stride = gridDim.x * blockDim.x;
    const int total4 = N_NODES * D_IN / 4;
    float4 z = make_float4(0.f, 0.f, 0.f, 0.f);
    for (int j = i; j < total4; j += stride)
        ((float4*)g_agg)[j] = z;
    for (int j = i; j < N_NODES; j += stride)
        g_cnt[j] = 0.f;
}

// ---------------------------------------------------------------------------
// Kernel 1: edge scatter. One warp per edge, RED.128 vector reductions.
// ---------------------------------------------------------------------------
__global__ void edge_kernel(const float* __restrict__ x,
                            const int* __restrict__ ei) {
    int w = blockIdx.x * (blockDim.x >> 5) + (threadIdx.x >> 5);
    if (w >= N_EDGES) return;
    int lane = threadIdx.x & 31;

    int src = ei[w];
    int dst = ei[N_EDGES + w];

    float4 v = ((const float4*)(x + (long long)src * D_IN))[lane];
    float* p = g_agg + (long long)dst * D_IN + lane * 4;
    asm volatile("red.global.add.v4.f32 [%0], {%1,%2,%3,%4};"
                 :: "l"(p), "f"(v.x), "f"(v.y), "f"(v.z), "f"(v.w)
                 : "memory");
    if (lane == 0)
        atomicAdd(&g_cnt[dst], 1.0f);
}

// ---------------------------------------------------------------------------
// Kernel 2: build fp16 weight image (W_cat^T, [n][k] layout)
// ---------------------------------------------------------------------------
__global__ void wconv_kernel(const float* __restrict__ wl,
                             const float* __restrict__ wr) {
    int idx = blockIdx.x * blockDim.x + threadIdx.x;
    if (idx >= 256 * 256) return;
    int n = idx >> 8;
    int k = idx & 255;
    float v = (k < 128) ? wl[k * 256 + n] : wr[(k - 128) * 256 + n];
    g_Wh[idx] = __float2half_rn(v);
}

// ---------------------------------------------------------------------------
// PTX helpers (family-portable: sm_75/80+)
// ---------------------------------------------------------------------------
__device__ __forceinline__ uint32_t smem_u32(const void* p) {
    uint32_t a;
    asm("{ .reg .u64 t; cvta.to.shared.u64 t, %1; cvt.u32.u64 %0, t; }"
        : "=r"(a) : "l"(p));
    return a;
}
__device__ __forceinline__ void mma_f16(float* d, const uint32_t* a,
                                        uint32_t b0, uint32_t b1) {
    asm volatile(
        "mma.sync.aligned.m16n8k16.row.col.f32.f16.f16.f32 "
        "{%0,%1,%2,%3}, {%4,%5,%6,%7}, {%8,%9}, {%0,%1,%2,%3};"
        : "+f"(d[0]), "+f"(d[1]), "+f"(d[2]), "+f"(d[3])
        : "r"(a[0]), "r"(a[1]), "r"(a[2]), "r"(a[3]), "r"(b0), "r"(b1));
}
#define LDSM4(d0, d1, d2, d3, addr) \
    asm volatile("ldmatrix.sync.aligned.m8n8.x4.shared.b16 {%0,%1,%2,%3}, [%4];" \
        : "=r"(d0), "=r"(d1), "=r"(d2), "=r"(d3) : "r"(addr))
#define CPASYNC16(dst, src) \
    asm volatile("cp.async.ca.shared.global [%0], [%1], 16;" :: "r"(dst), "l"(src))
#define CPCOMMIT() asm volatile("cp.async.commit_group;" ::: "memory")
#define CPWAIT0()  asm volatile("cp.async.wait_group 0;" ::: "memory")

// ---------------------------------------------------------------------------
// Kernel 3: fp16 1-pass mma.sync node kernel (A and B single fp16 images).
// Block = 256 threads (8 warps), M=64 nodes, N=256, K=256 in 4 chunks of 64.
// Warp tile M32 x N64. A and B double-buffered; register epilogue.
//
// SMEM/CTA (93,952 B -> 2 CTAs/SM):
//   A bufs [2 buf][64 rows][72 halfs]  @ 0        (18,432)
//   B bufs [2 buf][256 rows][72 halfs] @ 18,432   (73,728)
//   s_bl [256] f32                     @ 92,160
//   s_inv [64] f32                     @ 93,184
//   epilogue overlays: s_part 16K @0; s_wh @16,384; s_bh @33,792
// ---------------------------------------------------------------------------
#define AST     144           // bytes per smem row (64 halfs + 16B pad)
#define A_IMG   9216          // 64*144
#define B_OFF   18432
#define B_IMG   36864         // 256*144
#define OFF_BL  92160
#define OFF_INV 93184
#define SMEM_DYN 93952
#define E_WH  16384
#define E_BH  33792

__global__ __launch_bounds__(256, 2) void node_mma_kernel(
    const float* __restrict__ x,
    const float* __restrict__ wp, const float* __restrict__ bp,
    const float* __restrict__ ws, const float* __restrict__ bs,
    const float* __restrict__ bl,
    float* __restrict__ out)
{
    extern __shared__ float4 smem4[];
    char* smem = (char*)smem4;
    const uint32_t sb = smem_u32(smem);
    float* s_bl  = (float*)(smem + OFF_BL);
    float* s_inv = (float*)(smem + OFF_INV);

    const int t    = threadIdx.x;
    const int w    = t >> 5;
    const int lane = t & 31;
    const int lq   = lane >> 2;
    const int lr   = (lane & 3) * 2;
    const long long base = (long long)blockIdx.x * 64;

    if (t < 64) {
        long long node = base + t;
        if (node >= N_NODES) node = N_NODES - 1;
        s_inv[t] = 1.0f / fmaxf(g_cnt[node], 1.0f);
    }
    if (t < 256) s_bl[t] = bl[t];
    __syncthreads();

    const int m0    = (w & 1) * 32;    // 2 M-strips
    const int nbase = (w >> 1) * 64;   // 4 N-strips

    float acc[64];
#pragma unroll
    for (int i = 0; i < 64; i++) acc[i] = 0.f;

    // ---- staging helpers (k=64 chunks) ----
    auto stageB = [&](int c, int buf) {   // 256 rows x 128B via cp.async
        const char* gs = (const char*)&g_Wh[0];
#pragma unroll
        for (int it = 0; it < 8; it++) {
            int i = t + it * 256;         // 0..2047
            int n = i >> 3, q = i & 7;
            uint32_t dst = sb + B_OFF + buf * B_IMG + n * AST + q * 16;
            CPASYNC16(dst, gs + n * 512 + c * 128 + q * 16);
        }
    };
    auto stageA = [&](int c, int buf) {   // 64 rows x 64 k = 1024 float4
#pragma unroll
        for (int it = 0; it < 4; it++) {
            int i = t + it * 256;         // 0..1023
            int m = i >> 4, kl = (i & 15) * 4;
            long long node = base + m;
            if (node >= N_NODES) node = N_NODES - 1;
            const float* src = (c < 2)
                ? (g_agg + node * D_IN + c * 64 + kl)
                : (x + node * D_IN + (c - 2) * 64 + kl);
            float4 vv = *(const float4*)src;
            if (c < 2) {
                float inv = s_inv[m];
                vv.x *= inv; vv.y *= inv; vv.z *= inv; vv.w *= inv;
            }
            __half h0 = __float2half_rn(vv.x);
            __half h1 = __float2half_rn(vv.y);
            __half h2 = __float2half_rn(vv.z);
            __half h3 = __float2half_rn(vv.w);
            uint2 hp;
            hp.x = (uint32_t)__half_as_ushort(h0) | ((uint32_t)__half_as_ushort(h1) << 16);
            hp.y = (uint32_t)__half_as_ushort(h2) | ((uint32_t)__half_as_ushort(h3) << 16);
            *(uint2*)(smem + buf * A_IMG + m * AST + kl * 2) = hp;
        }
    };

    // ---- prologue: chunk 0 into buffer 0 ----
    stageB(0, 0); CPCOMMIT();
    stageA(0, 0);
    CPWAIT0();
    __syncthreads();

    const int tt    = lane >> 3;
    const int arow  = ((tt & 1) * 8) + (lane & 7);
    const int acol2 = ((tt >> 1) * 8) * 2;

    // ---- mainloop: 4 chunks, DMA for c+1 overlaps MMAs of c ----
    for (int c = 0; c < 4; c++) {
        int cur = c & 1, nxt = cur ^ 1;
        if (c < 3) {
            stageB(c + 1, nxt); CPCOMMIT();
            stageA(c + 1, nxt);
        }

        const uint32_t Ab = sb + cur * A_IMG;
        const uint32_t Bb = sb + B_OFF + cur * B_IMG;
#pragma unroll
        for (int ks = 0; ks < 4; ks++) {
            int kb = ks * 32;             // 16 halfs = 32B per k-step
            uint32_t a0[4], a1[4], b[4][4];
            uint32_t ad = Ab + (m0 + arow) * AST + kb + acol2;
            LDSM4(a0[0], a0[1], a0[2], a0[3], ad);
            LDSM4(a1[0], a1[1], a1[2], a1[3], ad + 16 * AST);
#pragma unroll
            for (int j = 0; j < 4; j++) {
                uint32_t bd = Bb + (nbase + j * 16 + arow) * AST + kb + acol2;
                LDSM4(b[j][0], b[j][1], b[j][2], b[j][3], bd);
            }
#pragma unroll
            for (int j = 0; j < 4; j++) {
                int nt0 = j * 2, nt1 = j * 2 + 1;
                mma_f16(acc + nt0 * 4,      a0, b[j][0], b[j][2]);
                mma_f16(acc + nt1 * 4,      a0, b[j][1], b[j][3]);
                mma_f16(acc + 32 + nt0 * 4, a1, b[j][0], b[j][2]);
                mma_f16(acc + 32 + nt1 * 4, a1, b[j][1], b[j][3]);
            }
        }
        if (c < 3) CPWAIT0();
        __syncthreads();
    }

    // ---- epilogue: overlay A/B region (register-resident heads) ----
    float* s_part = (float*)smem;              // [4 nstrip][64 m][16]
    float* s_wh   = (float*)(smem + E_WH);     // [256][17]
    float* s_bh   = (float*)(smem + E_BH);

    for (int i = t; i < 13 * 256; i += 256) {
        int j = i & 255, cc = i >> 8;
        s_wh[j * 17 + cc] = (cc < 7) ? wp[j * 7 + cc] : ws[j * 6 + (cc - 7)];
    }
    if (t < 16) s_bh[t] = (t < 7) ? bp[t] : (t < 13 ? bs[t - 7] : 0.f);
    __syncthreads();

    const int nstrip = w >> 1;
#pragma unroll
    for (int mi = 0; mi < 2; mi++) {
        float pr0[13], pr1[13];
#pragma unroll
        for (int cc = 0; cc < 13; cc++) { pr0[cc] = 0.f; pr1[cc] = 0.f; }
#pragma unroll
        for (int nt = 0; nt < 8; nt++) {
            int col0 = nbase + nt * 8 + lr;
            float b0 = s_bl[col0], b1 = s_bl[col0 + 1];
            const float* d = acc + mi * 32 + nt * 4;
            float h00 = fmaxf(d[0] + b0, 0.f), h01 = fmaxf(d[1] + b1, 0.f);
            float h10 = fmaxf(d[2] + b0, 0.f), h11 = fmaxf(d[3] + b1, 0.f);
            const float* w0 = s_wh + col0 * 17;
            const float* w1 = w0 + 17;
#pragma unroll
            for (int cc = 0; cc < 13; cc++) {
                float wa = w0[cc], wb = w1[cc];
                pr0[cc] = fmaf(h00, wa, fmaf(h01, wb, pr0[cc]));
                pr1[cc] = fmaf(h10, wa, fmaf(h11, wb, pr1[cc]));
            }
        }
#pragma unroll
        for (int cc = 0; cc < 13; cc++) {
            pr0[cc] += __shfl_xor_sync(0xffffffff, pr0[cc], 1);
            pr0[cc] += __shfl_xor_sync(0xffffffff, pr0[cc], 2);
            pr1[cc] += __shfl_xor_sync(0xffffffff, pr1[cc], 1);
            pr1[cc] += __shfl_xor_sync(0xffffffff, pr1[cc], 2);
        }
        if ((lane & 3) == 0) {
            int r = m0 + mi * 16 + lq;
#pragma unroll
            for (int cc = 0; cc < 13; cc++) {
                s_part[nstrip * 1024 + r * 16 + cc]       = pr0[cc];
                s_part[nstrip * 1024 + (r + 8) * 16 + cc] = pr1[cc];
            }
        }
    }
    __syncthreads();

    // final reduce + log_softmax + writeout
    if (t < 64) {
        long long node = base + t;
        if (node < N_NODES) {
            float o[13];
#pragma unroll
            for (int cc = 0; cc < 13; cc++) {
                o[cc] = s_bh[cc] + s_part[t * 16 + cc] + s_part[1024 + t * 16 + cc]
                      + s_part[2048 + t * 16 + cc] + s_part[3072 + t * 16 + cc];
            }
            float mx = o[0];
#pragma unroll
            for (int cc = 1; cc < 7; cc++) mx = fmaxf(mx, o[cc]);
            float s = 0.f;
#pragma unroll
            for (int cc = 0; cc < 7; cc++) s += __expf(o[cc] - mx);
            float lse = mx + __logf(s);
#pragma unroll
            for (int cc = 0; cc < 7; cc++) out[node * 7 + cc] = o[cc] - lse;

            mx = o[7];
#pragma unroll
            for (int cc = 8; cc < 13; cc++) mx = fmaxf(mx, o[cc]);
            s = 0.f;
#pragma unroll
            for (int cc = 7; cc < 13; cc++) s += __expf(o[cc] - mx);
            lse = mx + __logf(s);
            float* out2 = out + (long long)N_NODES * 7;
#pragma unroll
            for (int cc = 0; cc < 6; cc++) out2[node * 6 + cc] = o[7 + cc] - lse;
        }
    }
}

// ---------------------------------------------------------------------------
extern "C" void kernel_launch(void* const* d_in, const int* in_sizes, int n_in,
                              void* d_out, int out_size) {
    const float* x  = (const float*)d_in[0];
    const int*   ei = (const int*)d_in[1];
    const float* wl = (const float*)d_in[2];
    const float* bl = (const float*)d_in[3];
    const float* wr = (const float*)d_in[4];
    const float* wp = (const float*)d_in[5];
    const float* bp = (const float*)d_in[6];
    const float* ws = (const float*)d_in[7];
    const float* bs = (const float*)d_in[8];
    float* out = (float*)d_out;

    cudaFuncSetAttribute(node_mma_kernel,
                         cudaFuncAttributeMaxDynamicSharedMemorySize, SMEM_DYN);

    zero_kernel<<<512, 256>>>();
    wconv_kernel<<<256, 256>>>(wl, wr);

    int edge_blocks = (N_EDGES + 7) / 8;   // one warp per edge
    edge_kernel<<<edge_blocks, 256>>>(x, ei);

    int node_blocks = (N_NODES + 63) / 64;   // 1563
    node_mma_kernel<<<node_blocks, 256, SMEM_DYN>>>(x, wp, bp, ws, bs, bl, out);
}

// round 13
// speedup vs baseline: 1.9485x; 1.2173x over previous
#include <cuda_runtime.h>
#include <cuda_fp16.h>
#include <cstdint>

#define N_NODES 100000
#define N_EDGES 625000
#define D_IN    128
#define D_HID   256
#define NSCAN   100352        // 392 * 256 >= N_NODES + 1
#define NBLK    392

// ---------------------------------------------------------------------------
// Scratch (__device__ globals; allocation-free rule)
// ---------------------------------------------------------------------------
__device__ int    g_off[NSCAN];        // CSR offsets (exclusive prefix)
__device__ int    g_bsum[NBLK];        // scan block sums
__device__ int    g_cur[N_NODES];      // scatter cursors
__device__ int    g_csr[N_EDGES];      // CSR adjacency (src per slot)
__device__ __half g_aggh[(size_t)N_NODES * D_IN];   // mean-aggregated, fp16
__device__ __half g_xh[(size_t)N_NODES * D_IN];     // x converted to fp16
// Weight image W_cat^T: [n (256)][k (256)] fp16 (512B rows).
__device__ __half g_Wh[256 * 256];

// ---------------------------------------------------------------------------
// Kernel P0: zero the histogram/offsets
// ---------------------------------------------------------------------------
__global__ void prep_kernel() {
    int i = blockIdx.x * blockDim.x + threadIdx.x;   // 98*256 = 25088 int4
    ((int4*)g_off)[i] = make_int4(0, 0, 0, 0);
}

// ---------------------------------------------------------------------------
// Kernel P1: degree histogram into g_off[dst+1]
// ---------------------------------------------------------------------------
__global__ void hist_kernel(const int* __restrict__ ei) {
    int e = blockIdx.x * blockDim.x + threadIdx.x;
    if (e < N_EDGES)
        atomicAdd(&g_off[ei[N_EDGES + e] + 1], 1);
}

// ---------------------------------------------------------------------------
// Kernel P2a: per-block inclusive scan (256 elems/block)
// ---------------------------------------------------------------------------
__global__ void scan_block_kernel() {
    __shared__ int s[256];
    int tid = threadIdx.x;
    int i = blockIdx.x * 256 + tid;
    s[tid] = g_off[i];
#pragma unroll
    for (int off = 1; off < 256; off <<= 1) {
        __syncthreads();
        int tmp = (tid >= off) ? s[tid - off] : 0;
        __syncthreads();
        s[tid] += tmp;
    }
    __syncthreads();
    g_off[i] = s[tid];
    if (tid == 255) g_bsum[blockIdx.x] = s[255];
}

// ---------------------------------------------------------------------------
// Kernel P2b: scan the block sums (single block)
// ---------------------------------------------------------------------------
__global__ void scan_top_kernel() {
    __shared__ int s[512];
    int tid = threadIdx.x;
    s[tid] = (tid < NBLK) ? g_bsum[tid] : 0;
#pragma unroll
    for (int off = 1; off < 512; off <<= 1) {
        __syncthreads();
        int tmp = (tid >= off) ? s[tid - off] : 0;
        __syncthreads();
        s[tid] += tmp;
    }
    __syncthreads();
    if (tid < NBLK) g_bsum[tid] = s[tid];
}

// ---------------------------------------------------------------------------
// Kernel P2c: add block offsets; init scatter cursors
// ---------------------------------------------------------------------------
__global__ void scan_add_kernel() {
    int tid = threadIdx.x;
    int b = blockIdx.x;
    int i = b * 256 + tid;
    int add = (b > 0) ? g_bsum[b - 1] : 0;
    int val = g_off[i] + add;
    g_off[i] = val;
    if (i < N_NODES) g_cur[i] = val;
}

// ---------------------------------------------------------------------------
// Kernel P3: scatter edges into CSR slots
// ---------------------------------------------------------------------------
__global__ void scatter_kernel(const int* __restrict__ ei) {
    int e = blockIdx.x * blockDim.x + threadIdx.x;
    if (e < N_EDGES) {
        int src = ei[e];
        int dst = ei[N_EDGES + e];
        int idx = atomicAdd(&g_cur[dst], 1);
        g_csr[idx] = src;
    }
}

// ---------------------------------------------------------------------------
// Kernel P4: gather-aggregate (warp per node) + x -> fp16 conversion
// ---------------------------------------------------------------------------
__global__ void gather_kernel(const float* __restrict__ x) {
    int n    = blockIdx.x * 8 + (threadIdx.x >> 5);   // 12500*8 = 100000
    int lane = threadIdx.x & 31;

    // convert this node's own x row to fp16
    const float4* xr = (const float4*)(x + (long long)n * D_IN);
    float4 xv = xr[lane];
    {
        __half2 h01 = __floats2half2_rn(xv.x, xv.y);
        __half2 h23 = __floats2half2_rn(xv.z, xv.w);
        uint2 u;
        u.x = *reinterpret_cast<uint32_t*>(&h01);
        u.y = *reinterpret_cast<uint32_t*>(&h23);
        *(uint2*)(g_xh + (long long)n * D_IN + lane * 4) = u;
    }

    // gather-sum neighbor rows
    int beg = g_off[n], end = g_off[n + 1];
    float4 a = make_float4(0.f, 0.f, 0.f, 0.f);
    int s_next = (beg < end) ? g_csr[beg] : 0;
    for (int e = beg; e < end; e++) {
        int s_cur = s_next;
        if (e + 1 < end) s_next = g_csr[e + 1];
        float4 v = ((const float4*)(x + (long long)s_cur * D_IN))[lane];
        a.x += v.x; a.y += v.y; a.z += v.z; a.w += v.w;
    }
    float inv = (end > beg) ? 1.f / (float)(end - beg) : 0.f;
    __half2 h01 = __floats2half2_rn(a.x * inv, a.y * inv);
    __half2 h23 = __floats2half2_rn(a.z * inv, a.w * inv);
    uint2 u;
    u.x = *reinterpret_cast<uint32_t*>(&h01);
    u.y = *reinterpret_cast<uint32_t*>(&h23);
    *(uint2*)(g_aggh + (long long)n * D_IN + lane * 4) = u;
}

// ---------------------------------------------------------------------------
// Kernel W: build fp16 weight image (W_cat^T, [n][k] layout)
// ---------------------------------------------------------------------------
__global__ void wconv_kernel(const float* __restrict__ wl,
                             const float* __restrict__ wr) {
    int idx = blockIdx.x * blockDim.x + threadIdx.x;
    if (idx >= 256 * 256) return;
    int n = idx >> 8;
    int k = idx & 255;
    float v = (k < 128) ? wl[k * 256 + n] : wr[(k - 128) * 256 + n];
    g_Wh[idx] = __float2half_rn(v);
}

// ---------------------------------------------------------------------------
// PTX helpers (family-portable: sm_75/80+)
// ---------------------------------------------------------------------------
__device__ __forceinline__ uint32_t smem_u32(const void* p) {
    uint32_t a;
    asm("{ .reg .u64 t; cvta.to.shared.u64 t, %1; cvt.u32.u64 %0, t; }"
        : "=r"(a) : "l"(p));
    return a;
}
__device__ __forceinline__ void mma_f16(float* d, const uint32_t* a,
                                        uint32_t b0, uint32_t b1) {
    asm volatile(
        "mma.sync.aligned.m16n8k16.row.col.f32.f16.f16.f32 "
        "{%0,%1,%2,%3}, {%4,%5,%6,%7}, {%8,%9}, {%0,%1,%2,%3};"
        : "+f"(d[0]), "+f"(d[1]), "+f"(d[2]), "+f"(d[3])
        : "r"(a[0]), "r"(a[1]), "r"(a[2]), "r"(a[3]), "r"(b0), "r"(b1));
}
#define LDSM4(d0, d1, d2, d3, addr) \
    asm volatile("ldmatrix.sync.aligned.m8n8.x4.shared.b16 {%0,%1,%2,%3}, [%4];" \
        : "=r"(d0), "=r"(d1), "=r"(d2), "=r"(d3) : "r"(addr))
#define CPASYNC16(dst, src) \
    asm volatile("cp.async.ca.shared.global [%0], [%1], 16;" :: "r"(dst), "l"(src))
#define CPCOMMIT() asm volatile("cp.async.commit_group;" ::: "memory")
#define CPWAIT0()  asm volatile("cp.async.wait_group 0;" ::: "memory")

// ---------------------------------------------------------------------------
// Kernel N: fp16 1-pass mma.sync node kernel; A and B staged purely via
// cp.async from pre-converted fp16 images (no mainloop LDG latency).
// Block = 256 threads (8 warps), M=64 nodes, N=256, K=256 in 4 chunks of 64.
// Warp tile M32 x N64; A+B double-buffered; register epilogue.
//
// SMEM/CTA (93,184 B -> 2 CTAs/SM):
//   A bufs [2 buf][64 rows][72 halfs]  @ 0        (18,432)
//   B bufs [2 buf][256 rows][72 halfs] @ 18,432   (73,728)
//   s_bl [256] f32                     @ 92,160
//   epilogue overlays: s_part 16K @0; s_wh @16,384; s_bh @33,792
// ---------------------------------------------------------------------------
#define AST     144           // bytes per smem row (64 halfs + 16B pad)
#define A_IMG   9216          // 64*144
#define B_OFF   18432
#define B_IMG   36864         // 256*144
#define OFF_BL  92160
#define SMEM_DYN 93184
#define E_WH  16384
#define E_BH  33792

__global__ __launch_bounds__(256, 2) void node_mma_kernel(
    const float* __restrict__ wp, const float* __restrict__ bp,
    const float* __restrict__ ws, const float* __restrict__ bs,
    const float* __restrict__ bl,
    float* __restrict__ out)
{
    extern __shared__ float4 smem4[];
    char* smem = (char*)smem4;
    const uint32_t sb = smem_u32(smem);
    float* s_bl = (float*)(smem + OFF_BL);

    const int t    = threadIdx.x;
    const int w    = t >> 5;
    const int lane = t & 31;
    const int lq   = lane >> 2;
    const int lr   = (lane & 3) * 2;
    const long long base = (long long)blockIdx.x * 64;

    if (t < 256) s_bl[t] = bl[t];

    const int m0    = (w & 1) * 32;    // 2 M-strips
    const int nbase = (w >> 1) * 64;   // 4 N-strips

    float acc[64];
#pragma unroll
    for (int i = 0; i < 64; i++) acc[i] = 0.f;

    // ---- staging helpers (k=64 chunks), all cp.async ----
    auto stageB = [&](int c, int buf) {   // 256 rows x 128B
        const char* gs = (const char*)&g_Wh[0];
#pragma unroll
        for (int it = 0; it < 8; it++) {
            int i = t + it * 256;         // 0..2047
            int n = i >> 3, q = i & 7;
            uint32_t dst = sb + B_OFF + buf * B_IMG + n * AST + q * 16;
            CPASYNC16(dst, gs + n * 512 + c * 128 + q * 16);
        }
    };
    auto stageA = [&](int c, int buf) {   // 64 rows x 128B
        const __half* gsrc = (c < 2) ? g_aggh : g_xh;
        int koff = (c & 1) * 64;
#pragma unroll
        for (int it = 0; it < 2; it++) {
            int i = t + it * 256;         // 0..511
            int m = i >> 3, q = i & 7;
            long long node = base + m;
            if (node >= N_NODES) node = N_NODES - 1;
            uint32_t dst = sb + buf * A_IMG + m * AST + q * 16;
            CPASYNC16(dst, (const char*)(gsrc + node * D_IN + koff) + q * 16);
        }
    };

    // ---- prologue: chunk 0 into buffer 0 ----
    stageB(0, 0);
    stageA(0, 0);
    CPCOMMIT();
    CPWAIT0();
    __syncthreads();

    const int tt    = lane >> 3;
    const int arow  = ((tt & 1) * 8) + (lane & 7);
    const int acol2 = ((tt >> 1) * 8) * 2;

    // ---- mainloop: 4 chunks, DMA for c+1 overlaps MMAs of c ----
    for (int c = 0; c < 4; c++) {
        int cur = c & 1, nxt = cur ^ 1;
        if (c < 3) {
            stageB(c + 1, nxt);
            stageA(c + 1, nxt);
            CPCOMMIT();
        }

        const uint32_t Ab = sb + cur * A_IMG;
        const uint32_t Bb = sb + B_OFF + cur * B_IMG;
#pragma unroll
        for (int ks = 0; ks < 4; ks++) {
            int kb = ks * 32;             // 16 halfs = 32B per k-step
            uint32_t a0[4], a1[4], b[4][4];
            uint32_t ad = Ab + (m0 + arow) * AST + kb + acol2;
            LDSM4(a0[0], a0[1], a0[2], a0[3], ad);
            LDSM4(a1[0], a1[1], a1[2], a1[3], ad + 16 * AST);
#pragma unroll
            for (int j = 0; j < 4; j++) {
                uint32_t bd = Bb + (nbase + j * 16 + arow) * AST + kb + acol2;
                LDSM4(b[j][0], b[j][1], b[j][2], b[j][3], bd);
            }
#pragma unroll
            for (int j = 0; j < 4; j++) {
                int nt0 = j * 2, nt1 = j * 2 + 1;
                mma_f16(acc + nt0 * 4,      a0, b[j][0], b[j][2]);
                mma_f16(acc + nt1 * 4,      a0, b[j][1], b[j][3]);
                mma_f16(acc + 32 + nt0 * 4, a1, b[j][0], b[j][2]);
                mma_f16(acc + 32 + nt1 * 4, a1, b[j][1], b[j][3]);
            }
        }
        if (c < 3) CPWAIT0();
        __syncthreads();
    }

    // ---- epilogue: overlay A/B region (register-resident heads) ----
    float* s_part = (float*)smem;              // [4 nstrip][64 m][16]
    float* s_wh   = (float*)(smem + E_WH);     // [256][17]
    float* s_bh   = (float*)(smem + E_BH);

    for (int i = t; i < 13 * 256; i += 256) {
        int j = i & 255, cc = i >> 8;
        s_wh[j * 17 + cc] = (cc < 7) ? wp[j * 7 + cc] : ws[j * 6 + (cc - 7)];
    }
    if (t < 16) s_bh[t] = (t < 7) ? bp[t] : (t < 13 ? bs[t - 7] : 0.f);
    __syncthreads();

    const int nstrip = w >> 1;
#pragma unroll
    for (int mi = 0; mi < 2; mi++) {
        float pr0[13], pr1[13];
#pragma unroll
        for (int cc = 0; cc < 13; cc++) { pr0[cc] = 0.f; pr1[cc] = 0.f; }
#pragma unroll
        for (int nt = 0; nt < 8; nt++) {
            int col0 = nbase + nt * 8 + lr;
            float b0 = s_bl[col0], b1 = s_bl[col0 + 1];
            const float* d = acc + mi * 32 + nt * 4;
            float h00 = fmaxf(d[0] + b0, 0.f), h01 = fmaxf(d[1] + b1, 0.f);
            float h10 = fmaxf(d[2] + b0, 0.f), h11 = fmaxf(d[3] + b1, 0.f);
            const float* w0 = s_wh + col0 * 17;
            const float* w1 = w0 + 17;
#pragma unroll
            for (int cc = 0; cc < 13; cc++) {
                float wa = w0[cc], wb = w1[cc];
                pr0[cc] = fmaf(h00, wa, fmaf(h01, wb, pr0[cc]));
                pr1[cc] = fmaf(h10, wa, fmaf(h11, wb, pr1[cc]));
            }
        }
#pragma unroll
        for (int cc = 0; cc < 13; cc++) {
            pr0[cc] += __shfl_xor_sync(0xffffffff, pr0[cc], 1);
            pr0[cc] += __shfl_xor_sync(0xffffffff, pr0[cc], 2);
            pr1[cc] += __shfl_xor_sync(0xffffffff, pr1[cc], 1);
            pr1[cc] += __shfl_xor_sync(0xffffffff, pr1[cc], 2);
        }
        if ((lane & 3) == 0) {
            int r = m0 + mi * 16 + lq;
#pragma unroll
            for (int cc = 0; cc < 13; cc++) {
                s_part[nstrip * 1024 + r * 16 + cc]       = pr0[cc];
                s_part[nstrip * 1024 + (r + 8) * 16 + cc] = pr1[cc];
            }
        }
    }
    __syncthreads();

    // final reduce + log_softmax + writeout
    if (t < 64) {
        long long node = base + t;
        if (node < N_NODES) {
            float o[13];
#pragma unroll
            for (int cc = 0; cc < 13; cc++) {
                o[cc] = s_bh[cc] + s_part[t * 16 + cc] + s_part[1024 + t * 16 + cc]
                      + s_part[2048 + t * 16 + cc] + s_part[3072 + t * 16 + cc];
            }
            float mx = o[0];
#pragma unroll
            for (int cc = 1; cc < 7; cc++) mx = fmaxf(mx, o[cc]);
            float s = 0.f;
#pragma unroll
            for (int cc = 0; cc < 7; cc++) s += __expf(o[cc] - mx);
            float lse = mx + __logf(s);
#pragma unroll
            for (int cc = 0; cc < 7; cc++) out[node * 7 + cc] = o[cc] - lse;

            mx = o[7];
#pragma unroll
            for (int cc = 8; cc < 13; cc++) mx = fmaxf(mx, o[cc]);
            s = 0.f;
#pragma unroll
            for (int cc = 7; cc < 13; cc++) s += __expf(o[cc] - mx);
            lse = mx + __logf(s);
            float* out2 = out + (long long)N_NODES * 7;
#pragma unroll
            for (int cc = 0; cc < 6; cc++) out2[node * 6 + cc] = o[7 + cc] - lse;
        }
    }
}

// ---------------------------------------------------------------------------
extern "C" void kernel_launch(void* const* d_in, const int* in_sizes, int n_in,
                              void* d_out, int out_size) {
    const float* x  = (const float*)d_in[0];
    const int*   ei = (const int*)d_in[1];
    const float* wl = (const float*)d_in[2];
    const float* bl = (const float*)d_in[3];
    const float* wr = (const float*)d_in[4];
    const float* wp = (const float*)d_in[5];
    const float* bp = (const float*)d_in[6];
    const float* ws = (const float*)d_in[7];
    const float* bs = (const float*)d_in[8];
    float* out = (float*)d_out;

    cudaFuncSetAttribute(node_mma_kernel,
                         cudaFuncAttributeMaxDynamicSharedMemorySize, SMEM_DYN);

    // CSR build + fp16 image prep
    prep_kernel<<<98, 256>>>();
    hist_kernel<<<(N_EDGES + 255) / 256, 256>>>(ei);
    scan_block_kernel<<<NBLK, 256>>>();
    scan_top_kernel<<<1, 512>>>();
    scan_add_kernel<<<NBLK, 256>>>();
    scatter_kernel<<<(N_EDGES + 255) / 256, 256>>>(ei);
    gather_kernel<<<N_NODES / 8, 256>>>(x);
    wconv_kernel<<<256, 256>>>(wl, wr);

    int node_blocks = (N_NODES + 63) / 64;   // 1563
    node_mma_kernel<<<node_blocks, 256, SMEM_DYN>>>(wp, bp, ws, bs, bl, out);
}

// round 14
// speedup vs baseline: 1.9516x; 1.0016x over previous
#include <cuda_runtime.h>
#include <cuda_fp16.h>
#include <cstdint>

#define N_NODES 100000
#define N_EDGES 625000
#define D_IN    128
#define D_HID   256
#define NSCAN   100352        // 392 * 256 >= N_NODES + 1
#define NBLK    392

// ---------------------------------------------------------------------------
// Scratch (__device__ globals; allocation-free rule)
// ---------------------------------------------------------------------------
__device__ int    g_off[NSCAN];        // CSR offsets (exclusive prefix)
__device__ int    g_bsum[NBLK];        // scan block totals
__device__ int    g_cur[N_NODES];      // scatter cursors
__device__ int    g_csr[N_EDGES];      // CSR adjacency (src per slot)
__device__ __half g_aggh[(size_t)N_NODES * D_IN];   // mean-aggregated, fp16
__device__ __half g_xh[(size_t)N_NODES * D_IN];     // x converted to fp16
// Weight image W_cat^T: [n (256)][k (256)] fp16 (512B rows).
__device__ __half g_Wh[256 * 256];

// ---------------------------------------------------------------------------
// Kernel P0: zero the histogram/offsets
// ---------------------------------------------------------------------------
__global__ void prep_kernel() {
    int i = blockIdx.x * blockDim.x + threadIdx.x;   // 98*256 = 25088 int4
    ((int4*)g_off)[i] = make_int4(0, 0, 0, 0);
}

// ---------------------------------------------------------------------------
// Kernel X: convert x -> fp16 image (one float4 -> uint2 per thread)
// ---------------------------------------------------------------------------
__global__ void xconv_kernel(const float* __restrict__ x) {
    int i = blockIdx.x * blockDim.x + threadIdx.x;   // 3200000 float4
    float4 v = ((const float4*)x)[i];
    __half2 h01 = __floats2half2_rn(v.x, v.y);
    __half2 h23 = __floats2half2_rn(v.z, v.w);
    uint2 u;
    u.x = *reinterpret_cast<uint32_t*>(&h01);
    u.y = *reinterpret_cast<uint32_t*>(&h23);
    ((uint2*)g_xh)[i] = u;
}

// ---------------------------------------------------------------------------
// Kernel P1: degree histogram into g_off[dst+1]
// ---------------------------------------------------------------------------
__global__ void hist_kernel(const int* __restrict__ ei) {
    int e = blockIdx.x * blockDim.x + threadIdx.x;
    if (e < N_EDGES)
        atomicAdd(&g_off[ei[N_EDGES + e] + 1], 1);
}

// ---------------------------------------------------------------------------
// Kernel P2a: per-block inclusive scan (256 elems/block); store block totals
// ---------------------------------------------------------------------------
__global__ void scan_block_kernel() {
    __shared__ int s[256];
    int tid = threadIdx.x;
    int i = blockIdx.x * 256 + tid;
    s[tid] = g_off[i];
#pragma unroll
    for (int off = 1; off < 256; off <<= 1) {
        __syncthreads();
        int tmp = (tid >= off) ? s[tid - off] : 0;
        __syncthreads();
        s[tid] += tmp;
    }
    __syncthreads();
    g_off[i] = s[tid];
    if (tid == 255) g_bsum[blockIdx.x] = s[255];
}

// ---------------------------------------------------------------------------
// Kernel P2b: add block prefix (computed locally from g_bsum); init cursors.
// Replaces the separate single-block top-level scan.
// ---------------------------------------------------------------------------
__global__ void scan_add_kernel() {
    __shared__ int ssum[256];
    int tid = threadIdx.x;
    int b = blockIdx.x;

    int v = 0;
    for (int j = tid; j < b; j += 256) v += g_bsum[j];
    ssum[tid] = v;
#pragma unroll
    for (int off = 128; off > 0; off >>= 1) {
        __syncthreads();
        if (tid < off) ssum[tid] += ssum[tid + off];
    }
    __syncthreads();
    int add = ssum[0];

    int i = b * 256 + tid;
    int val = g_off[i] + add;
    g_off[i] = val;
    if (i < N_NODES) g_cur[i] = val;
}

// ---------------------------------------------------------------------------
// Kernel P3: scatter edges into CSR slots
// ---------------------------------------------------------------------------
__global__ void scatter_kernel(const int* __restrict__ ei) {
    int e = blockIdx.x * blockDim.x + threadIdx.x;
    if (e < N_EDGES) {
        int src = ei[e];
        int dst = ei[N_EDGES + e];
        int idx = atomicAdd(&g_cur[dst], 1);
        g_csr[idx] = src;
    }
}

// ---------------------------------------------------------------------------
// Kernel P4: gather-aggregate (warp per node) from fp16 image g_xh.
// Lane covers 4 halfs (8B) per neighbor row.
// ---------------------------------------------------------------------------
__global__ void gather_kernel() {
    int n    = blockIdx.x * 8 + (threadIdx.x >> 5);   // 12500*8 = 100000
    int lane = threadIdx.x & 31;

    int beg = g_off[n], end = g_off[n + 1];
    float a0 = 0.f, a1 = 0.f, a2 = 0.f, a3 = 0.f;
    int s_next = (beg < end) ? g_csr[beg] : 0;
    for (int e = beg; e < end; e++) {
        int s_cur = s_next;
        if (e + 1 < end) s_next = g_csr[e + 1];
        uint2 u = *(const uint2*)(g_xh + (long long)s_cur * D_IN + lane * 4);
        __half2 h01 = *reinterpret_cast<__half2*>(&u.x);
        __half2 h23 = *reinterpret_cast<__half2*>(&u.y);
        float2 f01 = __half22float2(h01);
        float2 f23 = __half22float2(h23);
        a0 += f01.x; a1 += f01.y; a2 += f23.x; a3 += f23.y;
    }
    float inv = (end > beg) ? 1.f / (float)(end - beg) : 0.f;
    __half2 h01 = __floats2half2_rn(a0 * inv, a1 * inv);
    __half2 h23 = __floats2half2_rn(a2 * inv, a3 * inv);
    uint2 u;
    u.x = *reinterpret_cast<uint32_t*>(&h01);
    u.y = *reinterpret_cast<uint32_t*>(&h23);
    *(uint2*)(g_aggh + (long long)n * D_IN + lane * 4) = u;
}

// ---------------------------------------------------------------------------
// Kernel W: build fp16 weight image (W_cat^T, [n][k] layout)
// ---------------------------------------------------------------------------
__global__ void wconv_kernel(const float* __restrict__ wl,
                             const float* __restrict__ wr) {
    int idx = blockIdx.x * blockDim.x + threadIdx.x;
    if (idx >= 256 * 256) return;
    int n = idx >> 8;
    int k = idx & 255;
    float v = (k < 128) ? wl[k * 256 + n] : wr[(k - 128) * 256 + n];
    g_Wh[idx] = __float2half_rn(v);
}

// ---------------------------------------------------------------------------
// PTX helpers (family-portable: sm_75/80+)
// ---------------------------------------------------------------------------
__device__ __forceinline__ uint32_t smem_u32(const void* p) {
    uint32_t a;
    asm("{ .reg .u64 t; cvta.to.shared.u64 t, %1; cvt.u32.u64 %0, t; }"
        : "=r"(a) : "l"(p));
    return a;
}
__device__ __forceinline__ void mma_f16(float* d, const uint32_t* a,
                                        uint32_t b0, uint32_t b1) {
    asm volatile(
        "mma.sync.aligned.m16n8k16.row.col.f32.f16.f16.f32 "
        "{%0,%1,%2,%3}, {%4,%5,%6,%7}, {%8,%9}, {%0,%1,%2,%3};"
        : "+f"(d[0]), "+f"(d[1]), "+f"(d[2]), "+f"(d[3])
        : "r"(a[0]), "r"(a[1]), "r"(a[2]), "r"(a[3]), "r"(b0), "r"(b1));
}
#define LDSM4(d0, d1, d2, d3, addr) \
    asm volatile("ldmatrix.sync.aligned.m8n8.x4.shared.b16 {%0,%1,%2,%3}, [%4];" \
        : "=r"(d0), "=r"(d1), "=r"(d2), "=r"(d3) : "r"(addr))
#define CPASYNC16(dst, src) \
    asm volatile("cp.async.ca.shared.global [%0], [%1], 16;" :: "r"(dst), "l"(src))
#define CPCOMMIT() asm volatile("cp.async.commit_group;" ::: "memory")
#define CPWAIT0()  asm volatile("cp.async.wait_group 0;" ::: "memory")

// ---------------------------------------------------------------------------
// Kernel N: fp16 1-pass mma.sync node kernel; A and B staged purely via
// cp.async from pre-converted fp16 images. (Unchanged from R13.)
// Block = 256 threads (8 warps), M=64 nodes, N=256, K=256 in 4 chunks of 64.
// Warp tile M32 x N64; A+B double-buffered; register epilogue.
//
// SMEM/CTA (93,184 B -> 2 CTAs/SM):
//   A bufs [2 buf][64 rows][72 halfs]  @ 0        (18,432)
//   B bufs [2 buf][256 rows][72 halfs] @ 18,432   (73,728)
//   s_bl [256] f32                     @ 92,160
//   epilogue overlays: s_part 16K @0; s_wh @16,384; s_bh @33,792
// ---------------------------------------------------------------------------
#define AST     144           // bytes per smem row (64 halfs + 16B pad)
#define A_IMG   9216          // 64*144
#define B_OFF   18432
#define B_IMG   36864         // 256*144
#define OFF_BL  92160
#define SMEM_DYN 93184
#define E_WH  16384
#define E_BH  33792

__global__ __launch_bounds__(256, 2) void node_mma_kernel(
    const float* __restrict__ wp, const float* __restrict__ bp,
    const float* __restrict__ ws, const float* __restrict__ bs,
    const float* __restrict__ bl,
    float* __restrict__ out)
{
    extern __shared__ float4 smem4[];
    char* smem = (char*)smem4;
    const uint32_t sb = smem_u32(smem);
    float* s_bl = (float*)(smem + OFF_BL);

    const int t    = threadIdx.x;
    const int w    = t >> 5;
    const int lane = t & 31;
    const int lq   = lane >> 2;
    const int lr   = (lane & 3) * 2;
    const long long base = (long long)blockIdx.x * 64;

    if (t < 256) s_bl[t] = bl[t];

    const int m0    = (w & 1) * 32;    // 2 M-strips
    const int nbase = (w >> 1) * 64;   // 4 N-strips

    float acc[64];
#pragma unroll
    for (int i = 0; i < 64; i++) acc[i] = 0.f;

    // ---- staging helpers (k=64 chunks), all cp.async ----
    auto stageB = [&](int c, int buf) {   // 256 rows x 128B
        const char* gs = (const char*)&g_Wh[0];
#pragma unroll
        for (int it = 0; it < 8; it++) {
            int i = t + it * 256;         // 0..2047
            int n = i >> 3, q = i & 7;
            uint32_t dst = sb + B_OFF + buf * B_IMG + n * AST + q * 16;
            CPASYNC16(dst, gs + n * 512 + c * 128 + q * 16);
        }
    };
    auto stageA = [&](int c, int buf) {   // 64 rows x 128B
        const __half* gsrc = (c < 2) ? g_aggh : g_xh;
        int koff = (c & 1) * 64;
#pragma unroll
        for (int it = 0; it < 2; it++) {
            int i = t + it * 256;         // 0..511
            int m = i >> 3, q = i & 7;
            long long node = base + m;
            if (node >= N_NODES) node = N_NODES - 1;
            uint32_t dst = sb + buf * A_IMG + m * AST + q * 16;
            CPASYNC16(dst, (const char*)(gsrc + node * D_IN + koff) + q * 16);
        }
    };

    // ---- prologue: chunk 0 into buffer 0 ----
    stageB(0, 0);
    stageA(0, 0);
    CPCOMMIT();
    CPWAIT0();
    __syncthreads();

    const int tt    = lane >> 3;
    const int arow  = ((tt & 1) * 8) + (lane & 7);
    const int acol2 = ((tt >> 1) * 8) * 2;

    // ---- mainloop: 4 chunks, DMA for c+1 overlaps MMAs of c ----
    for (int c = 0; c < 4; c++) {
        int cur = c & 1, nxt = cur ^ 1;
        if (c < 3) {
            stageB(c + 1, nxt);
            stageA(c + 1, nxt);
            CPCOMMIT();
        }

        const uint32_t Ab = sb + cur * A_IMG;
        const uint32_t Bb = sb + B_OFF + cur * B_IMG;
#pragma unroll
        for (int ks = 0; ks < 4; ks++) {
            int kb = ks * 32;             // 16 halfs = 32B per k-step
            uint32_t a0[4], a1[4], b[4][4];
            uint32_t ad = Ab + (m0 + arow) * AST + kb + acol2;
            LDSM4(a0[0], a0[1], a0[2], a0[3], ad);
            LDSM4(a1[0], a1[1], a1[2], a1[3], ad + 16 * AST);
#pragma unroll
            for (int j = 0; j < 4; j++) {
                uint32_t bd = Bb + (nbase + j * 16 + arow) * AST + kb + acol2;
                LDSM4(b[j][0], b[j][1], b[j][2], b[j][3], bd);
            }
#pragma unroll
            for (int j = 0; j < 4; j++) {
                int nt0 = j * 2, nt1 = j * 2 + 1;
                mma_f16(acc + nt0 * 4,      a0, b[j][0], b[j][2]);
                mma_f16(acc + nt1 * 4,      a0, b[j][1], b[j][3]);
                mma_f16(acc + 32 + nt0 * 4, a1, b[j][0], b[j][2]);
                mma_f16(acc + 32 + nt1 * 4, a1, b[j][1], b[j][3]);
            }
        }
        if (c < 3) CPWAIT0();
        __syncthreads();
    }

    // ---- epilogue: overlay A/B region (register-resident heads) ----
    float* s_part = (float*)smem;              // [4 nstrip][64 m][16]
    float* s_wh   = (float*)(smem + E_WH);     // [256][17]
    float* s_bh   = (float*)(smem + E_BH);

    for (int i = t; i < 13 * 256; i += 256) {
        int j = i & 255, cc = i >> 8;
        s_wh[j * 17 + cc] = (cc < 7) ? wp[j * 7 + cc] : ws[j * 6 + (cc - 7)];
    }
    if (t < 16) s_bh[t] = (t < 7) ? bp[t] : (t < 13 ? bs[t - 7] : 0.f);
    __syncthreads();

    const int nstrip = w >> 1;
#pragma unroll
    for (int mi = 0; mi < 2; mi++) {
        float pr0[13], pr1[13];
#pragma unroll
        for (int cc = 0; cc < 13; cc++) { pr0[cc] = 0.f; pr1[cc] = 0.f; }
#pragma unroll
        for (int nt = 0; nt < 8; nt++) {
            int col0 = nbase + nt * 8 + lr;
            float b0 = s_bl[col0], b1 = s_bl[col0 + 1];
            const float* d = acc + mi * 32 + nt * 4;
            float h00 = fmaxf(d[0] + b0, 0.f), h01 = fmaxf(d[1] + b1, 0.f);
            float h10 = fmaxf(d[2] + b0, 0.f), h11 = fmaxf(d[3] + b1, 0.f);
            const float* w0 = s_wh + col0 * 17;
            const float* w1 = w0 + 17;
#pragma unroll
            for (int cc = 0; cc < 13; cc++) {
                float wa = w0[cc], wb = w1[cc];
                pr0[cc] = fmaf(h00, wa, fmaf(h01, wb, pr0[cc]));
                pr1[cc] = fmaf(h10, wa, fmaf(h11, wb, pr1[cc]));
            }
        }
#pragma unroll
        for (int cc = 0; cc < 13; cc++) {
            pr0[cc] += __shfl_xor_sync(0xffffffff, pr0[cc], 1);
            pr0[cc] += __shfl_xor_sync(0xffffffff, pr0[cc], 2);
            pr1[cc] += __shfl_xor_sync(0xffffffff, pr1[cc], 1);
            pr1[cc] += __shfl_xor_sync(0xffffffff, pr1[cc], 2);
        }
        if ((lane & 3) == 0) {
            int r = m0 + mi * 16 + lq;
#pragma unroll
            for (int cc = 0; cc < 13; cc++) {
                s_part[nstrip * 1024 + r * 16 + cc]       = pr0[cc];
                s_part[nstrip * 1024 + (r + 8) * 16 + cc] = pr1[cc];
            }
        }
    }
    __syncthreads();

    // final reduce + log_softmax + writeout
    if (t < 64) {
        long long node = base + t;
        if (node < N_NODES) {
            float o[13];
#pragma unroll
            for (int cc = 0; cc < 13; cc++) {
                o[cc] = s_bh[cc] + s_part[t * 16 + cc] + s_part[1024 + t * 16 + cc]
                      + s_part[2048 + t * 16 + cc] + s_part[3072 + t * 16 + cc];
            }
            float mx = o[0];
#pragma unroll
            for (int cc = 1; cc < 7; cc++) mx = fmaxf(mx, o[cc]);
            float s = 0.f;
#pragma unroll
            for (int cc = 0; cc < 7; cc++) s += __expf(o[cc] - mx);
            float lse = mx + __logf(s);
#pragma unroll
            for (int cc = 0; cc < 7; cc++) out[node * 7 + cc] = o[cc] - lse;

            mx = o[7];
#pragma unroll
            for (int cc = 8; cc < 13; cc++) mx = fmaxf(mx, o[cc]);
            s = 0.f;
#pragma unroll
            for (int cc = 7; cc < 13; cc++) s += __expf(o[cc] - mx);
            lse = mx + __logf(s);
            float* out2 = out + (long long)N_NODES * 7;
#pragma unroll
            for (int cc = 0; cc < 6; cc++) out2[node * 6 + cc] = o[7 + cc] - lse;
        }
    }
}

// ---------------------------------------------------------------------------
extern "C" void kernel_launch(void* const* d_in, const int* in_sizes, int n_in,
                              void* d_out, int out_size) {
    const float* x  = (const float*)d_in[0];
    const int*   ei = (const int*)d_in[1];
    const float* wl = (const float*)d_in[2];
    const float* bl = (const float*)d_in[3];
    const float* wr = (const float*)d_in[4];
    const float* wp = (const float*)d_in[5];
    const float* bp = (const float*)d_in[6];
    const float* ws = (const float*)d_in[7];
    const float* bs = (const float*)d_in[8];
    float* out = (float*)d_out;

    cudaFuncSetAttribute(node_mma_kernel,
                         cudaFuncAttributeMaxDynamicSharedMemorySize, SMEM_DYN);

    // CSR build + fp16 image prep
    prep_kernel<<<98, 256>>>();
    xconv_kernel<<<(N_NODES * D_IN / 4) / 256, 256>>>(x);
    hist_kernel<<<(N_EDGES + 255) / 256, 256>>>(ei);
    scan_block_kernel<<<NBLK, 256>>>();
    scan_add_kernel<<<NBLK, 256>>>();
    scatter_kernel<<<(N_EDGES + 255) / 256, 256>>>(ei);
    gather_kernel<<<N_NODES / 8, 256>>>();
    wconv_kernel<<<256, 256>>>(wl, wr);

    int node_blocks = (N_NODES + 63) / 64;   // 1563
    node_mma_kernel<<<node_blocks, 256, SMEM_DYN>>>(wp, bp, ws, bs, bl, out);
}